// round 1
// baseline (speedup 1.0000x reference)
#include <cuda_runtime.h>

#define NB   8
#define NT   2048
#define NC   768
#define NH   64

// scratch for q = x @ Wq  (also serves as k and v)
__device__ float g_q[NB * NT * NH];

// ---------------------------------------------------------------------------
// Projection: q[16384,64] = x[16384,768] @ Wq[768,64]
// BM=64 rows per block, full N=64, BK=32, 256 threads, 4x4 microtile.
// ---------------------------------------------------------------------------
__global__ __launch_bounds__(256) void proj_kernel(const float* __restrict__ x,
                                                   const float* __restrict__ Wq) {
    __shared__ float As[64][32];
    __shared__ float Bs[32][64];
    const int tid = threadIdx.x;
    const int tx = tid & 15;          // 0..15 -> 4 output cols each
    const int ty = tid >> 4;          // 0..15 -> 4 output rows each
    const int r0 = blockIdx.x * 64;

    float acc[4][4];
#pragma unroll
    for (int i = 0; i < 4; i++)
#pragma unroll
        for (int j = 0; j < 4; j++) acc[i][j] = 0.f;

    for (int c0 = 0; c0 < NC; c0 += 32) {
        // load x tile 64x32 (512 float4)
#pragma unroll
        for (int u = 0; u < 2; u++) {
            int e  = tid + u * 256;
            int rr = e >> 3;
            int cc = (e & 7) << 2;
            *(float4*)&As[rr][cc] =
                *(const float4*)&x[(size_t)(r0 + rr) * NC + c0 + cc];
        }
        // load Wq tile 32x64 (512 float4)
#pragma unroll
        for (int u = 0; u < 2; u++) {
            int e  = tid + u * 256;
            int rr = e >> 4;
            int cc = (e & 15) << 2;
            *(float4*)&Bs[rr][cc] =
                *(const float4*)&Wq[(size_t)(c0 + rr) * NH + cc];
        }
        __syncthreads();
#pragma unroll
        for (int k = 0; k < 32; k++) {
            float a[4];
#pragma unroll
            for (int i = 0; i < 4; i++) a[i] = As[ty * 4 + i][k];
            float4 b4 = *(float4*)&Bs[k][tx * 4];
            float bq[4] = {b4.x, b4.y, b4.z, b4.w};
#pragma unroll
            for (int i = 0; i < 4; i++)
#pragma unroll
                for (int j = 0; j < 4; j++)
                    acc[i][j] = fmaf(a[i], bq[j], acc[i][j]);
        }
        __syncthreads();
    }
#pragma unroll
    for (int i = 0; i < 4; i++) {
        float4 v = make_float4(acc[i][0], acc[i][1], acc[i][2], acc[i][3]);
        *(float4*)&g_q[(size_t)(r0 + ty * 4 + i) * NH + tx * 4] = v;
    }
}

// ---------------------------------------------------------------------------
// Causal flash attention with relative bias. q == k == v == g_q.
// Block: 64 query rows, 256 threads (4 threads per row, each owns 16 of H=64).
// Key tiles of 32 rows staged in SMEM; online softmax; scores in registers.
// Heavy tiles (large tile index -> long key loops) launched first.
// ---------------------------------------------------------------------------
__global__ __launch_bounds__(256, 2) void flash_kernel(const float* __restrict__ rel,
                                                       float* __restrict__ out) {
    __shared__ float Ks[32][64];      // 8 KB: key/value tile
    __shared__ float rel_sh[4096];    // 16 KB: full rel_table

    const int tid  = threadIdx.x;
    const int b    = blockIdx.y;
    const int tile = (int)(gridDim.x - 1) - (int)blockIdx.x; // reversed order
    const int t0   = tile * 64;
    const int warp = tid >> 5;
    const int lane = tid & 31;
    const int r    = warp * 8 + (lane & 7);   // row within block (0..63)
    const int t    = t0 + r;                  // global query index
    const int h0   = (lane >> 3) * 16;        // this thread's 16-wide H slice

    for (int i = tid; i < 4095; i += 256) rel_sh[i] = rel[i];

    // my q fragment
    float q[16];
    const float* qrow = &g_q[((size_t)b * NT + t) * NH + h0];
#pragma unroll
    for (int u = 0; u < 4; u++) {
        float4 v = *(const float4*)&qrow[u * 4];
        q[u * 4 + 0] = v.x; q[u * 4 + 1] = v.y;
        q[u * 4 + 2] = v.z; q[u * 4 + 3] = v.w;
    }

    float O[16];
#pragma unroll
    for (int i = 0; i < 16; i++) O[i] = 0.f;
    float m = -1e30f, l = 0.f;

    const int nkt = 2 * tile + 2;   // key tiles of 32 covering s <= t0+63
    for (int kt = 0; kt < nkt; kt++) {
        const int s0 = kt * 32;
        __syncthreads();
        // fill key tile 32x64 (512 float4, 2 per thread) — also includes rel_sh barrier
#pragma unroll
        for (int u = 0; u < 2; u++) {
            int e  = tid + u * 256;
            int rr = e >> 4;
            int cc = (e & 15) << 2;
            *(float4*)&Ks[rr][cc] =
                *(const float4*)&g_q[((size_t)b * NT + s0 + rr) * NH + cc];
        }
        __syncthreads();

        const int bbase = s0 - t + 2047;   // rel index base (always in [0,4095))
        float sc[32];
        float tmax = -1e30f;
#pragma unroll
        for (int j = 0; j < 32; j++) {
            float p = 0.f;
#pragma unroll
            for (int u = 0; u < 4; u++) {
                float4 kv = *(float4*)&Ks[j][h0 + u * 4];
                p = fmaf(q[u * 4 + 0], kv.x, p);
                p = fmaf(q[u * 4 + 1], kv.y, p);
                p = fmaf(q[u * 4 + 2], kv.z, p);
                p = fmaf(q[u * 4 + 3], kv.w, p);
            }
            // combine the 4 H-quarters of this row
            p += __shfl_xor_sync(0xffffffffu, p, 8);
            p += __shfl_xor_sync(0xffffffffu, p, 16);
            p = fmaf(p, 0.125f, rel_sh[bbase + j]);   // * H^-0.5 + bias
            if (s0 + j > t) p = -1e30f;               // causal mask
            sc[j] = p;
            tmax = fmaxf(tmax, p);
        }

        const float newm = fmaxf(m, tmax);
        const float corr = __expf(m - newm);
        l *= corr;
#pragma unroll
        for (int i = 0; i < 16; i++) O[i] *= corr;

#pragma unroll
        for (int j = 0; j < 32; j++) {
            float pj = __expf(sc[j] - newm);
            l += pj;
#pragma unroll
            for (int u = 0; u < 4; u++) {
                float4 kv = *(float4*)&Ks[j][h0 + u * 4];   // v tile == k tile
                O[u * 4 + 0] = fmaf(pj, kv.x, O[u * 4 + 0]);
                O[u * 4 + 1] = fmaf(pj, kv.y, O[u * 4 + 1]);
                O[u * 4 + 2] = fmaf(pj, kv.z, O[u * 4 + 2]);
                O[u * 4 + 3] = fmaf(pj, kv.w, O[u * 4 + 3]);
            }
        }
        m = newm;
    }

    const float inv = 1.f / l;
    float* orow = &out[((size_t)b * NT + t) * NH + h0];
#pragma unroll
    for (int u = 0; u < 4; u++) {
        float4 v = make_float4(O[u * 4 + 0] * inv, O[u * 4 + 1] * inv,
                               O[u * 4 + 2] * inv, O[u * 4 + 3] * inv);
        *(float4*)&orow[u * 4] = v;
    }
}

extern "C" void kernel_launch(void* const* d_in, const int* in_sizes, int n_in,
                              void* d_out, int out_size) {
    const float* x   = (const float*)d_in[0];
    const float* Wq  = (const float*)d_in[1];
    const float* rel = (const float*)d_in[2];
    float* out = (float*)d_out;

    proj_kernel<<<NB * NT / 64, 256>>>(x, Wq);

    dim3 grid(NT / 64, NB);
    flash_kernel<<<grid, 256>>>(rel, out);
}

// round 2
// speedup vs baseline: 8.8363x; 8.8363x over previous
#include <cuda_runtime.h>

#define NB   8
#define NT   2048
#define NC   768
#define NH   64

// scratch for q = x @ Wq  (also serves as k and v)
__device__ float g_q[NB * NT * NH];

// ---------------------------------------------------------------------------
// Projection: q[16384,64] = x[16384,768] @ Wq[768,64]
// ---------------------------------------------------------------------------
__global__ __launch_bounds__(256) void proj_kernel(const float* __restrict__ x,
                                                   const float* __restrict__ Wq) {
    __shared__ float As[64][32];
    __shared__ float Bs[32][64];
    const int tid = threadIdx.x;
    const int tx = tid & 15;
    const int ty = tid >> 4;
    const int r0 = blockIdx.x * 64;

    float acc[4][4];
#pragma unroll
    for (int i = 0; i < 4; i++)
#pragma unroll
        for (int j = 0; j < 4; j++) acc[i][j] = 0.f;

    for (int c0 = 0; c0 < NC; c0 += 32) {
#pragma unroll
        for (int u = 0; u < 2; u++) {
            int e  = tid + u * 256;
            int rr = e >> 3;
            int cc = (e & 7) << 2;
            *(float4*)&As[rr][cc] =
                *(const float4*)&x[(size_t)(r0 + rr) * NC + c0 + cc];
        }
#pragma unroll
        for (int u = 0; u < 2; u++) {
            int e  = tid + u * 256;
            int rr = e >> 4;
            int cc = (e & 15) << 2;
            *(float4*)&Bs[rr][cc] =
                *(const float4*)&Wq[(size_t)(c0 + rr) * NH + cc];
        }
        __syncthreads();
#pragma unroll
        for (int k = 0; k < 32; k++) {
            float a[4];
#pragma unroll
            for (int i = 0; i < 4; i++) a[i] = As[ty * 4 + i][k];
            float4 b4 = *(float4*)&Bs[k][tx * 4];
            float bq[4] = {b4.x, b4.y, b4.z, b4.w};
#pragma unroll
            for (int i = 0; i < 4; i++)
#pragma unroll
                for (int j = 0; j < 4; j++)
                    acc[i][j] = fmaf(a[i], bq[j], acc[i][j]);
        }
        __syncthreads();
    }
#pragma unroll
    for (int i = 0; i < 4; i++) {
        float4 v = make_float4(acc[i][0], acc[i][1], acc[i][2], acc[i][3]);
        *(float4*)&g_q[(size_t)(r0 + ty * 4 + i) * NH + tx * 4] = v;
    }
}

// ---------------------------------------------------------------------------
// Flash attention, SGEMM-style register tiling.
// Block: 64 query rows x 64-key tiles, 256 threads (16x16), 4x4 microtile.
// Each block processes query tiles {31-pair, pair} -> 33 key-tile tasks/block.
// ---------------------------------------------------------------------------
#define SM_QT   0                 // [64][64] h-major:   Qt[h][row]
#define SM_KT   4096              // [64][64] h-major:   Kt[h][key]
#define SM_VN   8192              // [64][64] key-major: Vn[key][h]
#define SM_PT   12288             // [64][65] key-major: Pt[key][row], padded
#define SM_BS   (12288 + 4160)    // [128] bias slice
#define SMEM_FLOATS (SM_BS + 128)
#define SMEM_BYTES  (SMEM_FLOATS * 4)

__global__ __launch_bounds__(256) void flash2_kernel(const float* __restrict__ rel,
                                                     float* __restrict__ out) {
    extern __shared__ float sm[];
    float* Qt = sm + SM_QT;
    float* Kt = sm + SM_KT;
    float* Vn = sm + SM_VN;
    float* Pt = sm + SM_PT;
    float* bs = sm + SM_BS;

    const int tid = threadIdx.x;
    const int tx  = tid & 15;       // key / H quarter  (4 each)
    const int ty  = tid >> 4;       // query row quarter (4 each)
    const int b   = blockIdx.y;
    const int pair = blockIdx.x;    // 0..15

    for (int pi = 0; pi < 2; pi++) {
        const int tile = (pi == 0) ? (31 - pair) : pair;
        const int t0   = tile * 64;
        __syncthreads();

        // stage Q transposed: Qt[h][row]
#pragma unroll
        for (int u = 0; u < 4; u++) {
            int e   = tid + u * 256;
            int row = e & 63;
            int g   = e >> 6;
            float4 v = *(const float4*)&g_q[((size_t)b * NT + t0 + row) * NH + g * 4];
            Qt[(4 * g + 0) * 64 + row] = v.x;
            Qt[(4 * g + 1) * 64 + row] = v.y;
            Qt[(4 * g + 2) * 64 + row] = v.z;
            Qt[(4 * g + 3) * 64 + row] = v.w;
        }

        float m[4], l[4], O[4][4];
#pragma unroll
        for (int i = 0; i < 4; i++) {
            m[i] = -1e30f; l[i] = 0.f;
#pragma unroll
            for (int j = 0; j < 4; j++) O[i][j] = 0.f;
        }

        for (int kt = 0; kt <= tile; kt++) {
            const int s0 = kt * 64;
            __syncthreads();
            // stage K transposed: Kt[h][key]
#pragma unroll
            for (int u = 0; u < 4; u++) {
                int e   = tid + u * 256;
                int key = e & 63;
                int g   = e >> 6;
                float4 v = *(const float4*)&g_q[((size_t)b * NT + s0 + key) * NH + g * 4];
                Kt[(4 * g + 0) * 64 + key] = v.x;
                Kt[(4 * g + 1) * 64 + key] = v.y;
                Kt[(4 * g + 2) * 64 + key] = v.z;
                Kt[(4 * g + 3) * 64 + key] = v.w;
            }
            // stage V natural: Vn[key][h]  (coalesced)
#pragma unroll
            for (int u = 0; u < 4; u++) {
                int e   = tid + u * 256;
                int key = e >> 4;
                int g   = e & 15;
                *(float4*)&Vn[key * 64 + g * 4] =
                    *(const float4*)&g_q[((size_t)b * NT + s0 + key) * NH + g * 4];
            }
            // stage bias slice: indices d = (s-t)+2047 for this tile pair
            if (tid < 127) bs[tid] = rel[s0 - t0 + 1984 + tid];
            __syncthreads();

            // ---- S = Q K^T (4x4 outer-product accumulation) ----
            float s[4][4];
#pragma unroll
            for (int i = 0; i < 4; i++)
#pragma unroll
                for (int j = 0; j < 4; j++) s[i][j] = 0.f;

#pragma unroll 8
            for (int k = 0; k < 64; k++) {
                float4 a4 = *(float4*)&Qt[k * 64 + ty * 4];
                float4 b4 = *(float4*)&Kt[k * 64 + tx * 4];
                float a[4] = {a4.x, a4.y, a4.z, a4.w};
                float bb[4] = {b4.x, b4.y, b4.z, b4.w};
#pragma unroll
                for (int i = 0; i < 4; i++)
#pragma unroll
                    for (int j = 0; j < 4; j++)
                        s[i][j] = fmaf(a[i], bb[j], s[i][j]);
            }

            // ---- bias + mask + online softmax ----
            const bool diag = (kt == tile);
#pragma unroll
            for (int i = 0; i < 4; i++) {
                const int ri = ty * 4 + i;
                float tmax = -1e30f;
#pragma unroll
                for (int j = 0; j < 4; j++) {
                    const int kj = tx * 4 + j;
                    float v = fmaf(s[i][j], 0.125f, bs[kj - ri + 63]);
                    if (diag && kj > ri) v = -1e30f;
                    s[i][j] = v;
                    tmax = fmaxf(tmax, v);
                }
                tmax = fmaxf(tmax, __shfl_xor_sync(0xffffffffu, tmax, 1));
                tmax = fmaxf(tmax, __shfl_xor_sync(0xffffffffu, tmax, 2));
                tmax = fmaxf(tmax, __shfl_xor_sync(0xffffffffu, tmax, 4));
                tmax = fmaxf(tmax, __shfl_xor_sync(0xffffffffu, tmax, 8));
                const float nm   = fmaxf(m[i], tmax);
                const float corr = __expf(m[i] - nm);
                float rs = 0.f;
#pragma unroll
                for (int j = 0; j < 4; j++) {
                    float p = __expf(s[i][j] - nm);
                    s[i][j] = p;
                    rs += p;
                }
                rs += __shfl_xor_sync(0xffffffffu, rs, 1);
                rs += __shfl_xor_sync(0xffffffffu, rs, 2);
                rs += __shfl_xor_sync(0xffffffffu, rs, 4);
                rs += __shfl_xor_sync(0xffffffffu, rs, 8);
                l[i] = l[i] * corr + rs;
#pragma unroll
                for (int j = 0; j < 4; j++) O[i][j] *= corr;
                m[i] = nm;
            }

            // ---- stage P transposed: Pt[key][row] (padded 65) ----
#pragma unroll
            for (int j = 0; j < 4; j++)
#pragma unroll
                for (int i = 0; i < 4; i++)
                    Pt[(tx * 4 + j) * 65 + ty * 4 + i] = s[i][j];
            __syncthreads();

            // ---- O += P V (outer product over keys) ----
#pragma unroll 4
            for (int kk = 0; kk < 64; kk++) {
                float4 b4 = *(float4*)&Vn[kk * 64 + tx * 4];
                float bb[4] = {b4.x, b4.y, b4.z, b4.w};
                float pa[4];
#pragma unroll
                for (int i = 0; i < 4; i++) pa[i] = Pt[kk * 65 + ty * 4 + i];
#pragma unroll
                for (int i = 0; i < 4; i++)
#pragma unroll
                    for (int j = 0; j < 4; j++)
                        O[i][j] = fmaf(pa[i], bb[j], O[i][j]);
            }
        }

        // ---- epilogue ----
#pragma unroll
        for (int i = 0; i < 4; i++) {
            const float inv = 1.f / l[i];
            float4 v = make_float4(O[i][0] * inv, O[i][1] * inv,
                                   O[i][2] * inv, O[i][3] * inv);
            *(float4*)&out[((size_t)b * NT + t0 + ty * 4 + i) * NH + tx * 4] = v;
        }
    }
}

extern "C" void kernel_launch(void* const* d_in, const int* in_sizes, int n_in,
                              void* d_out, int out_size) {
    const float* x   = (const float*)d_in[0];
    const float* Wq  = (const float*)d_in[1];
    const float* rel = (const float*)d_in[2];
    float* out = (float*)d_out;

    static bool attr_set = false;
    if (!attr_set) {
        cudaFuncSetAttribute(flash2_kernel,
                             cudaFuncAttributeMaxDynamicSharedMemorySize,
                             SMEM_BYTES);
        attr_set = true;
    }

    proj_kernel<<<NB * NT / 64, 256>>>(x, Wq);

    dim3 grid(16, NB);
    flash2_kernel<<<grid, 256, SMEM_BYTES>>>(rel, out);
}

// round 3
// speedup vs baseline: 15.2513x; 1.7260x over previous
#include <cuda_runtime.h>
#include <cuda_bf16.h>
#include <cstdint>

#define NB 8
#define NT 2048
#define NC 768
#define NH 64
#define QS 72   // padded bf16 row stride for SMEM tiles

__device__ __align__(16) __nv_bfloat16 g_qh[NB * NT * NH];
__device__ __align__(16) __nv_bfloat16 g_ql[NB * NT * NH];

__device__ __forceinline__ uint32_t packbf(float e0, float e1) {
    uint32_t r;
    asm("cvt.rn.bf16x2.f32 %0, %1, %2;" : "=r"(r) : "f"(e1), "f"(e0));
    return r;   // lower 16 bits = e0, upper = e1
}

__device__ __forceinline__ void mma_bf16(float* d, const uint32_t* a,
                                         uint32_t b0, uint32_t b1) {
    asm volatile("mma.sync.aligned.m16n8k16.row.col.f32.bf16.bf16.f32 "
                 "{%0,%1,%2,%3}, {%4,%5,%6,%7}, {%8,%9}, {%0,%1,%2,%3};"
                 : "+f"(d[0]), "+f"(d[1]), "+f"(d[2]), "+f"(d[3])
                 : "r"(a[0]), "r"(a[1]), "r"(a[2]), "r"(a[3]),
                   "r"(b0), "r"(b1));
}

// ---------------------------------------------------------------------------
// Projection: q[16384,64] = x[16384,768] @ Wq[768,64]  (fp32 exact)
// Epilogue writes bf16 hi/lo split of q.
// ---------------------------------------------------------------------------
__global__ __launch_bounds__(256) void proj_kernel(const float* __restrict__ x,
                                                   const float* __restrict__ Wq) {
    __shared__ float As[64][32];
    __shared__ float Bs[32][64];
    const int tid = threadIdx.x;
    const int tx = tid & 15;
    const int ty = tid >> 4;
    const int r0 = blockIdx.x * 64;

    float acc[4][4];
#pragma unroll
    for (int i = 0; i < 4; i++)
#pragma unroll
        for (int j = 0; j < 4; j++) acc[i][j] = 0.f;

    for (int c0 = 0; c0 < NC; c0 += 32) {
#pragma unroll
        for (int u = 0; u < 2; u++) {
            int e  = tid + u * 256;
            int rr = e >> 3;
            int cc = (e & 7) << 2;
            *(float4*)&As[rr][cc] =
                *(const float4*)&x[(size_t)(r0 + rr) * NC + c0 + cc];
        }
#pragma unroll
        for (int u = 0; u < 2; u++) {
            int e  = tid + u * 256;
            int rr = e >> 4;
            int cc = (e & 15) << 2;
            *(float4*)&Bs[rr][cc] =
                *(const float4*)&Wq[(size_t)(c0 + rr) * NH + cc];
        }
        __syncthreads();
#pragma unroll
        for (int k = 0; k < 32; k++) {
            float a[4];
#pragma unroll
            for (int i = 0; i < 4; i++) a[i] = As[ty * 4 + i][k];
            float4 b4 = *(float4*)&Bs[k][tx * 4];
            float bq[4] = {b4.x, b4.y, b4.z, b4.w};
#pragma unroll
            for (int i = 0; i < 4; i++)
#pragma unroll
                for (int j = 0; j < 4; j++)
                    acc[i][j] = fmaf(a[i], bq[j], acc[i][j]);
        }
        __syncthreads();
    }
#pragma unroll
    for (int i = 0; i < 4; i++) {
        size_t base = (size_t)(r0 + ty * 4 + i) * NH + tx * 4;
        uint32_t hp0 = packbf(acc[i][0], acc[i][1]);
        uint32_t hp1 = packbf(acc[i][2], acc[i][3]);
        float h0 = __uint_as_float(hp0 << 16);
        float h1 = __uint_as_float(hp0 & 0xffff0000u);
        float h2 = __uint_as_float(hp1 << 16);
        float h3 = __uint_as_float(hp1 & 0xffff0000u);
        uint32_t lp0 = packbf(acc[i][0] - h0, acc[i][1] - h1);
        uint32_t lp1 = packbf(acc[i][2] - h2, acc[i][3] - h3);
        *(uint2*)&g_qh[base] = make_uint2(hp0, hp1);
        *(uint2*)&g_ql[base] = make_uint2(lp0, lp1);
    }
}

// ---------------------------------------------------------------------------
// Tensor-core flash attention, bf16x3 emulation, online softmax.
// Block: 256 threads = 2 groups of 4 warps. Query tile = 64 rows.
// Group g handles key tiles kt = g, g+2, ... <= tile; merged at end.
// ---------------------------------------------------------------------------
#define SM_GRP0   18432
#define SM_GRPSZ  37376
#define SMEM_BYTES (SM_GRP0 + 2 * SM_GRPSZ)

__global__ __launch_bounds__(256) void flashT_kernel(const float* __restrict__ rel,
                                                     float* __restrict__ out) {
    extern __shared__ char smraw[];
    __nv_bfloat16* Qh = (__nv_bfloat16*)smraw;
    __nv_bfloat16* Ql = Qh + 64 * QS;

    const int tid  = threadIdx.x;
    const int w    = tid >> 5;
    const int lane = tid & 31;
    const int g    = w >> 2;        // group 0/1
    const int wi   = w & 3;         // warp in group -> rows 16*wi..+15
    const int l4   = lane >> 2;
    const int l2   = (lane & 3) << 1;
    const int tid128 = tid & 127;

    char* gbase = smraw + SM_GRP0 + g * SM_GRPSZ;
    __nv_bfloat16* Kh  = (__nv_bfloat16*)gbase;
    __nv_bfloat16* Kl  = Kh + 64 * QS;
    __nv_bfloat16* Vth = Kl + 64 * QS;
    __nv_bfloat16* Vtl = Vth + 64 * QS;
    float* bs = (float*)(gbase + 4 * 64 * QS * 2);

    float* Om = (float*)smraw;                 // merge scratch [64][65]
    float* Mm = (float*)(smraw + 16640);       // [64]
    float* Lm = Mm + 64;                       // [64]

    const int b    = blockIdx.y;
    const int pair = blockIdx.x;
    const int rbase = 16 * wi + l4;            // my d0/d1 row (d2/d3 = +8)

    for (int pi = 0; pi < 2; pi++) {
        const int tile = (pi == 0) ? (31 - pair) : pair;
        const int t0   = tile * 64;
        __syncthreads();
        // stage Q hi/lo
        {
            const __nv_bfloat16* sh = &g_qh[((size_t)b * NT + t0) * NH];
            const __nv_bfloat16* sl = &g_ql[((size_t)b * NT + t0) * NH];
#pragma unroll
            for (int u = 0; u < 2; u++) {
                int e   = tid + u * 256;
                int row = e >> 3, q4 = e & 7;
                *(uint4*)&Qh[row * QS + q4 * 8] = *(const uint4*)&sh[row * 64 + q4 * 8];
                *(uint4*)&Ql[row * QS + q4 * 8] = *(const uint4*)&sl[row * 64 + q4 * 8];
            }
        }
        __syncthreads();

        // Q fragments (A-frags), kept for the whole q-tile
        uint32_t qfh[4][4], qfl[4][4];
#pragma unroll
        for (int ks = 0; ks < 4; ks++) {
            int c = 16 * ks + l2;
            qfh[ks][0] = *(uint32_t*)&Qh[rbase * QS + c];
            qfh[ks][1] = *(uint32_t*)&Qh[(rbase + 8) * QS + c];
            qfh[ks][2] = *(uint32_t*)&Qh[rbase * QS + c + 8];
            qfh[ks][3] = *(uint32_t*)&Qh[(rbase + 8) * QS + c + 8];
            qfl[ks][0] = *(uint32_t*)&Ql[rbase * QS + c];
            qfl[ks][1] = *(uint32_t*)&Ql[(rbase + 8) * QS + c];
            qfl[ks][2] = *(uint32_t*)&Ql[rbase * QS + c + 8];
            qfl[ks][3] = *(uint32_t*)&Ql[(rbase + 8) * QS + c + 8];
        }

        float Oa[8][4];
#pragma unroll
        for (int nb = 0; nb < 8; nb++)
#pragma unroll
            for (int j = 0; j < 4; j++) Oa[nb][j] = 0.f;
        float mrow[2] = {-1e30f, -1e30f};
        float lrow[2] = {0.f, 0.f};

        for (int kt = g; kt <= tile; kt += 2) {
            const int s0 = kt * 64;
            asm volatile("bar.sync %0, %1;" :: "r"(1 + g), "r"(128) : "memory");
            // stage K (natural) and V^T, hi and lo
            {
                const __nv_bfloat16* kh = &g_qh[((size_t)b * NT + s0) * NH];
                const __nv_bfloat16* kl = &g_ql[((size_t)b * NT + s0) * NH];
#pragma unroll
                for (int u = 0; u < 4; u++) {
                    int e   = tid128 + u * 128;
                    int row = e >> 3, q4 = e & 7;
                    *(uint4*)&Kh[row * QS + q4 * 8] = *(const uint4*)&kh[row * 64 + q4 * 8];
                    *(uint4*)&Kl[row * QS + q4 * 8] = *(const uint4*)&kl[row * 64 + q4 * 8];
                }
                unsigned short* vh = (unsigned short*)Vth;
                unsigned short* vl = (unsigned short*)Vtl;
#pragma unroll
                for (int u = 0; u < 16; u++) {
                    int e  = tid128 + u * 128;
                    int s  = e >> 5, hp = e & 31;
                    uint32_t a = *(const uint32_t*)&kh[s * 64 + hp * 2];
                    uint32_t c = *(const uint32_t*)&kl[s * 64 + hp * 2];
                    vh[(2 * hp) * QS + s]     = (unsigned short)(a & 0xffffu);
                    vh[(2 * hp + 1) * QS + s] = (unsigned short)(a >> 16);
                    vl[(2 * hp) * QS + s]     = (unsigned short)(c & 0xffffu);
                    vl[(2 * hp + 1) * QS + s] = (unsigned short)(c >> 16);
                }
                if (tid128 < 127) bs[tid128] = rel[s0 - t0 + 1984 + tid128];
            }
            asm volatile("bar.sync %0, %1;" :: "r"(1 + g), "r"(128) : "memory");

            // ---- S = Q K^T (bf16x3) ----
            float sa[8][4];
#pragma unroll
            for (int nb = 0; nb < 8; nb++)
#pragma unroll
                for (int j = 0; j < 4; j++) sa[nb][j] = 0.f;
#pragma unroll
            for (int ks = 0; ks < 4; ks++) {
#pragma unroll
                for (int nb = 0; nb < 8; nb++) {
                    int rr = 8 * nb + l4, cc = 16 * ks + l2;
                    uint32_t bh0 = *(uint32_t*)&Kh[rr * QS + cc];
                    uint32_t bh1 = *(uint32_t*)&Kh[rr * QS + cc + 8];
                    uint32_t bl0 = *(uint32_t*)&Kl[rr * QS + cc];
                    uint32_t bl1 = *(uint32_t*)&Kl[rr * QS + cc + 8];
                    mma_bf16(sa[nb], qfh[ks], bh0, bh1);
                    mma_bf16(sa[nb], qfh[ks], bl0, bl1);
                    mma_bf16(sa[nb], qfl[ks], bh0, bh1);
                }
            }

            // ---- bias + causal mask + online softmax ----
            const bool diag = (kt == tile);
            float tmax0 = -1e30f, tmax1 = -1e30f;
#pragma unroll
            for (int nb = 0; nb < 8; nb++) {
                int c0 = 8 * nb + l2;
                float v0 = fmaf(sa[nb][0], 0.125f, bs[c0 - rbase + 63]);
                float v1 = fmaf(sa[nb][1], 0.125f, bs[c0 - rbase + 64]);
                float v2 = fmaf(sa[nb][2], 0.125f, bs[c0 - rbase + 55]);
                float v3 = fmaf(sa[nb][3], 0.125f, bs[c0 - rbase + 56]);
                if (diag) {
                    if (c0 > rbase)         v0 = -1e30f;
                    if (c0 + 1 > rbase)     v1 = -1e30f;
                    if (c0 > rbase + 8)     v2 = -1e30f;
                    if (c0 + 1 > rbase + 8) v3 = -1e30f;
                }
                sa[nb][0] = v0; sa[nb][1] = v1; sa[nb][2] = v2; sa[nb][3] = v3;
                tmax0 = fmaxf(tmax0, fmaxf(v0, v1));
                tmax1 = fmaxf(tmax1, fmaxf(v2, v3));
            }
            tmax0 = fmaxf(tmax0, __shfl_xor_sync(0xffffffffu, tmax0, 1));
            tmax0 = fmaxf(tmax0, __shfl_xor_sync(0xffffffffu, tmax0, 2));
            tmax1 = fmaxf(tmax1, __shfl_xor_sync(0xffffffffu, tmax1, 1));
            tmax1 = fmaxf(tmax1, __shfl_xor_sync(0xffffffffu, tmax1, 2));
            const float nm0 = fmaxf(mrow[0], tmax0);
            const float nm1 = fmaxf(mrow[1], tmax1);
            const float cr0 = __expf(mrow[0] - nm0);
            const float cr1 = __expf(mrow[1] - nm1);
            float rs0 = 0.f, rs1 = 0.f;
#pragma unroll
            for (int nb = 0; nb < 8; nb++) {
                float p0 = __expf(sa[nb][0] - nm0);
                float p1 = __expf(sa[nb][1] - nm0);
                float p2 = __expf(sa[nb][2] - nm1);
                float p3 = __expf(sa[nb][3] - nm1);
                sa[nb][0] = p0; sa[nb][1] = p1; sa[nb][2] = p2; sa[nb][3] = p3;
                rs0 += p0 + p1; rs1 += p2 + p3;
                Oa[nb][0] *= cr0; Oa[nb][1] *= cr0;
                Oa[nb][2] *= cr1; Oa[nb][3] *= cr1;
            }
            rs0 += __shfl_xor_sync(0xffffffffu, rs0, 1);
            rs0 += __shfl_xor_sync(0xffffffffu, rs0, 2);
            rs1 += __shfl_xor_sync(0xffffffffu, rs1, 1);
            rs1 += __shfl_xor_sync(0xffffffffu, rs1, 2);
            lrow[0] = lrow[0] * cr0 + rs0;
            lrow[1] = lrow[1] * cr1 + rs1;
            mrow[0] = nm0; mrow[1] = nm1;

            // ---- O += P V (bf16x3), P reused in-register as A-fragments ----
#pragma unroll
            for (int kb = 0; kb < 4; kb++) {
                uint32_t pah[4], pal[4];
                {
                    float p0 = sa[2 * kb][0],     p1 = sa[2 * kb][1];
                    float p2 = sa[2 * kb][2],     p3 = sa[2 * kb][3];
                    float p4 = sa[2 * kb + 1][0], p5 = sa[2 * kb + 1][1];
                    float p6 = sa[2 * kb + 1][2], p7 = sa[2 * kb + 1][3];
                    pah[0] = packbf(p0, p1); pah[1] = packbf(p2, p3);
                    pah[2] = packbf(p4, p5); pah[3] = packbf(p6, p7);
                    pal[0] = packbf(p0 - __uint_as_float(pah[0] << 16),
                                    p1 - __uint_as_float(pah[0] & 0xffff0000u));
                    pal[1] = packbf(p2 - __uint_as_float(pah[1] << 16),
                                    p3 - __uint_as_float(pah[1] & 0xffff0000u));
                    pal[2] = packbf(p4 - __uint_as_float(pah[2] << 16),
                                    p5 - __uint_as_float(pah[2] & 0xffff0000u));
                    pal[3] = packbf(p6 - __uint_as_float(pah[3] << 16),
                                    p7 - __uint_as_float(pah[3] & 0xffff0000u));
                }
#pragma unroll
                for (int nb = 0; nb < 8; nb++) {
                    int rr = 8 * nb + l4, cc = 16 * kb + l2;
                    uint32_t vh0 = *(uint32_t*)&Vth[rr * QS + cc];
                    uint32_t vh1 = *(uint32_t*)&Vth[rr * QS + cc + 8];
                    uint32_t vl0 = *(uint32_t*)&Vtl[rr * QS + cc];
                    uint32_t vl1 = *(uint32_t*)&Vtl[rr * QS + cc + 8];
                    mma_bf16(Oa[nb], pah, vh0, vh1);
                    mma_bf16(Oa[nb], pah, vl0, vl1);
                    mma_bf16(Oa[nb], pal, vh0, vh1);
                }
            }
        }

        // ---- merge the two groups' partials, write output ----
        __syncthreads();
        if (g == 1) {
#pragma unroll
            for (int nb = 0; nb < 8; nb++) {
                Om[rbase * 65 + 8 * nb + l2]           = Oa[nb][0];
                Om[rbase * 65 + 8 * nb + l2 + 1]       = Oa[nb][1];
                Om[(rbase + 8) * 65 + 8 * nb + l2]     = Oa[nb][2];
                Om[(rbase + 8) * 65 + 8 * nb + l2 + 1] = Oa[nb][3];
            }
            if ((lane & 3) == 0) {
                Mm[rbase] = mrow[0];     Lm[rbase] = lrow[0];
                Mm[rbase + 8] = mrow[1]; Lm[rbase + 8] = lrow[1];
            }
        }
        __syncthreads();
        if (g == 0) {
#pragma unroll
            for (int half = 0; half < 2; half++) {
                const int row = rbase + 8 * half;
                const float m1 = Mm[row], l1 = Lm[row];
                const float M  = fmaxf(mrow[half], m1);
                const float ea = __expf(mrow[half] - M);
                const float eb = __expf(m1 - M);
                const float inv = 1.f / (ea * lrow[half] + eb * l1);
                float* orow = &out[((size_t)b * NT + t0 + row) * NH];
#pragma unroll
                for (int nb = 0; nb < 8; nb++) {
                    int c = 8 * nb + l2;
                    float2 o2;
                    o2.x = (ea * Oa[nb][2 * half]     + eb * Om[row * 65 + c])     * inv;
                    o2.y = (ea * Oa[nb][2 * half + 1] + eb * Om[row * 65 + c + 1]) * inv;
                    *(float2*)&orow[c] = o2;
                }
            }
        }
    }
}

extern "C" void kernel_launch(void* const* d_in, const int* in_sizes, int n_in,
                              void* d_out, int out_size) {
    const float* x   = (const float*)d_in[0];
    const float* Wq  = (const float*)d_in[1];
    const float* rel = (const float*)d_in[2];
    float* out = (float*)d_out;

    static bool attr_set = false;
    if (!attr_set) {
        cudaFuncSetAttribute(flashT_kernel,
                             cudaFuncAttributeMaxDynamicSharedMemorySize,
                             SMEM_BYTES);
        attr_set = true;
    }

    proj_kernel<<<NB * NT / 64, 256>>>(x, Wq);

    dim3 grid(16, NB);
    flashT_kernel<<<grid, 256, SMEM_BYTES>>>(rel, out);
}

// round 4
// speedup vs baseline: 25.9735x; 1.7030x over previous
#include <cuda_runtime.h>
#include <cuda_bf16.h>
#include <cstdint>

#define NB 8
#define NT 2048
#define NC 768
#define NH 64
#define QS 72   // padded bf16 row stride for SMEM tiles

__device__ __align__(16) __nv_bfloat16 g_qh[NB * NT * NH];
__device__ __align__(16) __nv_bfloat16 g_ql[NB * NT * NH];
__device__ __align__(16) __nv_bfloat16 g_wh[NC * NH];
__device__ __align__(16) __nv_bfloat16 g_wl[NC * NH];

__device__ __forceinline__ uint32_t packbf(float e0, float e1) {
    uint32_t r;
    asm("cvt.rn.bf16x2.f32 %0, %1, %2;" : "=r"(r) : "f"(e1), "f"(e0));
    return r;   // lower 16 bits = e0, upper = e1
}

__device__ __forceinline__ void mma_bf16(float* d, const uint32_t* a,
                                         uint32_t b0, uint32_t b1) {
    asm volatile("mma.sync.aligned.m16n8k16.row.col.f32.bf16.bf16.f32 "
                 "{%0,%1,%2,%3}, {%4,%5,%6,%7}, {%8,%9}, {%0,%1,%2,%3};"
                 : "+f"(d[0]), "+f"(d[1]), "+f"(d[2]), "+f"(d[3])
                 : "r"(a[0]), "r"(a[1]), "r"(a[2]), "r"(a[3]),
                   "r"(b0), "r"(b1));
}

__device__ __forceinline__ void ldsm4(uint32_t* r, uint32_t addr) {
    asm volatile("ldmatrix.sync.aligned.m8n8.x4.shared.b16 {%0,%1,%2,%3}, [%4];"
                 : "=r"(r[0]), "=r"(r[1]), "=r"(r[2]), "=r"(r[3]) : "r"(addr));
}
__device__ __forceinline__ void ldsm4t(uint32_t* r, uint32_t addr) {
    asm volatile("ldmatrix.sync.aligned.m8n8.x4.trans.shared.b16 {%0,%1,%2,%3}, [%4];"
                 : "=r"(r[0]), "=r"(r[1]), "=r"(r[2]), "=r"(r[3]) : "r"(addr));
}

// ---------------------------------------------------------------------------
// prep: split Wq into bf16 hi/lo (natural [k=768][n=64])
// ---------------------------------------------------------------------------
__global__ void prep_w_kernel(const float* __restrict__ Wq) {
    int i = blockIdx.x * 256 + threadIdx.x;
    float v = Wq[i];
    __nv_bfloat16 h = __float2bfloat16(v);
    g_wh[i] = h;
    g_wl[i] = __float2bfloat16(v - __bfloat162float(h));
}

// ---------------------------------------------------------------------------
// Projection on tensor cores (bf16x3): q = x @ Wq, output split hi/lo.
// Block: 128 rows, 256 threads = 8 warps x 16 rows. k-chunks of 64.
// ---------------------------------------------------------------------------
#define PSMEM ((128 + 128 + 64 + 64) * QS * 2)

__global__ __launch_bounds__(256) void projT_kernel(const float* __restrict__ x) {
    extern __shared__ char psm[];
    __nv_bfloat16* Xh = (__nv_bfloat16*)psm;
    __nv_bfloat16* Xl = Xh + 128 * QS;
    __nv_bfloat16* Wh = Xl + 128 * QS;
    __nv_bfloat16* Wl = Wh + 64 * QS;

    const int tid  = threadIdx.x;
    const int w    = tid >> 5;
    const int lane = tid & 31;
    const int quad = lane >> 3;
    const int l4   = lane >> 2;
    const int l2   = (lane & 3) << 1;
    const int r0   = blockIdx.x * 128;

    const uint32_t Xh_u = (uint32_t)__cvta_generic_to_shared(Xh);
    const uint32_t Xl_u = (uint32_t)__cvta_generic_to_shared(Xl);
    const uint32_t Wh_u = (uint32_t)__cvta_generic_to_shared(Wh);
    const uint32_t Wl_u = (uint32_t)__cvta_generic_to_shared(Wl);

    const uint32_t xa = ((16 * w + 8 * (quad & 1) + (lane & 7)) * QS + 8 * (quad >> 1)) * 2;
    const uint32_t wb = ((8 * (quad & 1) + (lane & 7)) * QS + 8 * (quad >> 1)) * 2;

    float Oacc[8][4];
#pragma unroll
    for (int nb = 0; nb < 8; nb++)
#pragma unroll
        for (int j = 0; j < 4; j++) Oacc[nb][j] = 0.f;

    for (int c0 = 0; c0 < NC; c0 += 64) {
        __syncthreads();
        // stage x chunk: 128 rows x 64 cols, fp32 -> bf16 hi/lo
#pragma unroll
        for (int u = 0; u < 8; u++) {
            int e   = tid + u * 256;
            int row = e >> 4, g4 = e & 15;
            float4 v = *(const float4*)&x[(size_t)(r0 + row) * NC + c0 + g4 * 4];
            uint32_t h0 = packbf(v.x, v.y);
            uint32_t h1 = packbf(v.z, v.w);
            uint32_t l0 = packbf(v.x - __uint_as_float(h0 << 16),
                                 v.y - __uint_as_float(h0 & 0xffff0000u));
            uint32_t l1 = packbf(v.z - __uint_as_float(h1 << 16),
                                 v.w - __uint_as_float(h1 & 0xffff0000u));
            *(uint2*)&Xh[row * QS + g4 * 4] = make_uint2(h0, h1);
            *(uint2*)&Xl[row * QS + g4 * 4] = make_uint2(l0, l1);
        }
        // stage W chunk: 64 k-rows x 64 n
#pragma unroll
        for (int u = 0; u < 2; u++) {
            int e   = tid + u * 256;
            int row = e >> 3, q4 = e & 7;
            *(uint4*)&Wh[row * QS + q4 * 8] = *(const uint4*)&g_wh[(c0 + row) * NH + q4 * 8];
            *(uint4*)&Wl[row * QS + q4 * 8] = *(const uint4*)&g_wl[(c0 + row) * NH + q4 * 8];
        }
        __syncthreads();

        uint32_t ah[4][4], al[4][4];
#pragma unroll
        for (int ks = 0; ks < 4; ks++) {
            ldsm4(ah[ks], Xh_u + xa + 32 * ks);
            ldsm4(al[ks], Xl_u + xa + 32 * ks);
        }
#pragma unroll
        for (int ks = 0; ks < 4; ks++) {
#pragma unroll
            for (int nbp = 0; nbp < 4; nbp++) {
                uint32_t off = wb + (16 * ks * QS + 16 * nbp) * 2;
                uint32_t bh[4], bl[4];
                ldsm4t(bh, Wh_u + off);
                ldsm4t(bl, Wl_u + off);
                mma_bf16(Oacc[2 * nbp],     ah[ks], bh[0], bh[1]);
                mma_bf16(Oacc[2 * nbp],     ah[ks], bl[0], bl[1]);
                mma_bf16(Oacc[2 * nbp],     al[ks], bh[0], bh[1]);
                mma_bf16(Oacc[2 * nbp + 1], ah[ks], bh[2], bh[3]);
                mma_bf16(Oacc[2 * nbp + 1], ah[ks], bl[2], bl[3]);
                mma_bf16(Oacc[2 * nbp + 1], al[ks], bh[2], bh[3]);
            }
        }
    }

    // epilogue: split to hi/lo, write q
    const size_t row0 = (size_t)r0 + 16 * w + l4;
#pragma unroll
    for (int nb = 0; nb < 8; nb++) {
        int c = 8 * nb + l2;
        uint32_t hp0 = packbf(Oacc[nb][0], Oacc[nb][1]);
        uint32_t hp1 = packbf(Oacc[nb][2], Oacc[nb][3]);
        uint32_t lp0 = packbf(Oacc[nb][0] - __uint_as_float(hp0 << 16),
                              Oacc[nb][1] - __uint_as_float(hp0 & 0xffff0000u));
        uint32_t lp1 = packbf(Oacc[nb][2] - __uint_as_float(hp1 << 16),
                              Oacc[nb][3] - __uint_as_float(hp1 & 0xffff0000u));
        *(uint32_t*)&g_qh[row0 * NH + c]       = hp0;
        *(uint32_t*)&g_ql[row0 * NH + c]       = lp0;
        *(uint32_t*)&g_qh[(row0 + 8) * NH + c] = hp1;
        *(uint32_t*)&g_ql[(row0 + 8) * NH + c] = lp1;
    }
}

// ---------------------------------------------------------------------------
// Tensor-core flash attention, bf16x3, ldmatrix operands, V tile == K tile.
// Block: 256 threads = 2 groups of 4 warps; pair-scheduled q-tiles.
// ---------------------------------------------------------------------------
#define SM_GRP0   18432
#define SM_GRPSZ  18944
#define SMEM_BYTES (SM_GRP0 + 2 * SM_GRPSZ)

__global__ __launch_bounds__(256) void flashT_kernel(const float* __restrict__ rel,
                                                     float* __restrict__ out) {
    extern __shared__ char smraw[];
    __nv_bfloat16* Qh = (__nv_bfloat16*)smraw;
    __nv_bfloat16* Ql = Qh + 64 * QS;

    const int tid  = threadIdx.x;
    const int w    = tid >> 5;
    const int lane = tid & 31;
    const int g    = w >> 2;
    const int wi   = w & 3;
    const int quad = lane >> 3;
    const int l4   = lane >> 2;
    const int l2   = (lane & 3) << 1;
    const int tid128 = tid & 127;

    char* gbase = smraw + SM_GRP0 + g * SM_GRPSZ;
    __nv_bfloat16* Kh = (__nv_bfloat16*)gbase;
    __nv_bfloat16* Kl = Kh + 64 * QS;
    float* bs = (float*)(gbase + 2 * 64 * QS * 2);

    float* Om = (float*)smraw;
    float* Mm = (float*)(smraw + 16640);
    float* Lm = Mm + 64;

    const uint32_t Qh_u = (uint32_t)__cvta_generic_to_shared(Qh);
    const uint32_t Ql_u = (uint32_t)__cvta_generic_to_shared(Ql);
    const uint32_t Kh_u = (uint32_t)__cvta_generic_to_shared(Kh);
    const uint32_t Kl_u = (uint32_t)__cvta_generic_to_shared(Kl);

    // lane-offsets for ldmatrix
    const uint32_t qa  = ((16 * wi + 8 * (quad & 1) + (lane & 7)) * QS + 8 * (quad >> 1)) * 2;
    const uint32_t kqk = ((8 * (quad >> 1) + (lane & 7)) * QS + 8 * (quad & 1)) * 2;
    const uint32_t kpv = ((8 * (quad & 1) + (lane & 7)) * QS + 8 * (quad >> 1)) * 2;

    const int b    = blockIdx.y;
    const int pair = blockIdx.x;
    const int rbase = 16 * wi + l4;

    for (int pi = 0; pi < 2; pi++) {
        const int tile = (pi == 0) ? (31 - pair) : pair;
        const int t0   = tile * 64;
        __syncthreads();
        // stage Q hi/lo
        {
            const __nv_bfloat16* sh = &g_qh[((size_t)b * NT + t0) * NH];
            const __nv_bfloat16* sl = &g_ql[((size_t)b * NT + t0) * NH];
#pragma unroll
            for (int u = 0; u < 2; u++) {
                int e   = tid + u * 256;
                int row = e >> 3, q4 = e & 7;
                *(uint4*)&Qh[row * QS + q4 * 8] = *(const uint4*)&sh[row * 64 + q4 * 8];
                *(uint4*)&Ql[row * QS + q4 * 8] = *(const uint4*)&sl[row * 64 + q4 * 8];
            }
        }
        __syncthreads();

        uint32_t qfh[4][4], qfl[4][4];
#pragma unroll
        for (int ks = 0; ks < 4; ks++) {
            ldsm4(qfh[ks], Qh_u + qa + 32 * ks);
            ldsm4(qfl[ks], Ql_u + qa + 32 * ks);
        }

        float Oa[8][4];
#pragma unroll
        for (int nb = 0; nb < 8; nb++)
#pragma unroll
            for (int j = 0; j < 4; j++) Oa[nb][j] = 0.f;
        float mrow[2] = {-1e30f, -1e30f};
        float lrow[2] = {0.f, 0.f};

        for (int kt = g; kt <= tile; kt += 2) {
            const int s0 = kt * 64;
            asm volatile("bar.sync %0, %1;" :: "r"(1 + g), "r"(128) : "memory");
            // stage K (== V) natural layout, hi/lo
            {
                const __nv_bfloat16* kh = &g_qh[((size_t)b * NT + s0) * NH];
                const __nv_bfloat16* kl = &g_ql[((size_t)b * NT + s0) * NH];
#pragma unroll
                for (int u = 0; u < 4; u++) {
                    int e   = tid128 + u * 128;
                    int row = e >> 3, q4 = e & 7;
                    *(uint4*)&Kh[row * QS + q4 * 8] = *(const uint4*)&kh[row * 64 + q4 * 8];
                    *(uint4*)&Kl[row * QS + q4 * 8] = *(const uint4*)&kl[row * 64 + q4 * 8];
                }
                if (tid128 < 127) bs[tid128] = rel[s0 - t0 + 1984 + tid128];
            }
            asm volatile("bar.sync %0, %1;" :: "r"(1 + g), "r"(128) : "memory");

            // ---- S = Q K^T (bf16x3), B-frags via ldmatrix ----
            float sa[8][4];
#pragma unroll
            for (int nb = 0; nb < 8; nb++)
#pragma unroll
                for (int j = 0; j < 4; j++) sa[nb][j] = 0.f;
#pragma unroll
            for (int ks = 0; ks < 4; ks++) {
#pragma unroll
                for (int nbp = 0; nbp < 4; nbp++) {
                    uint32_t off = kqk + (16 * nbp * QS + 16 * ks) * 2;
                    uint32_t bh[4], bl[4];
                    ldsm4(bh, Kh_u + off);
                    ldsm4(bl, Kl_u + off);
                    mma_bf16(sa[2 * nbp],     qfh[ks], bh[0], bh[1]);
                    mma_bf16(sa[2 * nbp],     qfh[ks], bl[0], bl[1]);
                    mma_bf16(sa[2 * nbp],     qfl[ks], bh[0], bh[1]);
                    mma_bf16(sa[2 * nbp + 1], qfh[ks], bh[2], bh[3]);
                    mma_bf16(sa[2 * nbp + 1], qfh[ks], bl[2], bl[3]);
                    mma_bf16(sa[2 * nbp + 1], qfl[ks], bh[2], bh[3]);
                }
            }

            // ---- bias + causal mask + online softmax ----
            const bool diag = (kt == tile);
            float tmax0 = -1e30f, tmax1 = -1e30f;
#pragma unroll
            for (int nb = 0; nb < 8; nb++) {
                int c0 = 8 * nb + l2;
                float v0 = fmaf(sa[nb][0], 0.125f, bs[c0 - rbase + 63]);
                float v1 = fmaf(sa[nb][1], 0.125f, bs[c0 - rbase + 64]);
                float v2 = fmaf(sa[nb][2], 0.125f, bs[c0 - rbase + 55]);
                float v3 = fmaf(sa[nb][3], 0.125f, bs[c0 - rbase + 56]);
                if (diag) {
                    if (c0 > rbase)         v0 = -1e30f;
                    if (c0 + 1 > rbase)     v1 = -1e30f;
                    if (c0 > rbase + 8)     v2 = -1e30f;
                    if (c0 + 1 > rbase + 8) v3 = -1e30f;
                }
                sa[nb][0] = v0; sa[nb][1] = v1; sa[nb][2] = v2; sa[nb][3] = v3;
                tmax0 = fmaxf(tmax0, fmaxf(v0, v1));
                tmax1 = fmaxf(tmax1, fmaxf(v2, v3));
            }
            tmax0 = fmaxf(tmax0, __shfl_xor_sync(0xffffffffu, tmax0, 1));
            tmax0 = fmaxf(tmax0, __shfl_xor_sync(0xffffffffu, tmax0, 2));
            tmax1 = fmaxf(tmax1, __shfl_xor_sync(0xffffffffu, tmax1, 1));
            tmax1 = fmaxf(tmax1, __shfl_xor_sync(0xffffffffu, tmax1, 2));
            const float nm0 = fmaxf(mrow[0], tmax0);
            const float nm1 = fmaxf(mrow[1], tmax1);
            const float cr0 = __expf(mrow[0] - nm0);
            const float cr1 = __expf(mrow[1] - nm1);
            float rs0 = 0.f, rs1 = 0.f;
#pragma unroll
            for (int nb = 0; nb < 8; nb++) {
                float p0 = __expf(sa[nb][0] - nm0);
                float p1 = __expf(sa[nb][1] - nm0);
                float p2 = __expf(sa[nb][2] - nm1);
                float p3 = __expf(sa[nb][3] - nm1);
                sa[nb][0] = p0; sa[nb][1] = p1; sa[nb][2] = p2; sa[nb][3] = p3;
                rs0 += p0 + p1; rs1 += p2 + p3;
                Oa[nb][0] *= cr0; Oa[nb][1] *= cr0;
                Oa[nb][2] *= cr1; Oa[nb][3] *= cr1;
            }
            rs0 += __shfl_xor_sync(0xffffffffu, rs0, 1);
            rs0 += __shfl_xor_sync(0xffffffffu, rs0, 2);
            rs1 += __shfl_xor_sync(0xffffffffu, rs1, 1);
            rs1 += __shfl_xor_sync(0xffffffffu, rs1, 2);
            lrow[0] = lrow[0] * cr0 + rs0;
            lrow[1] = lrow[1] * cr1 + rs1;
            mrow[0] = nm0; mrow[1] = nm1;

            // ---- O += P V (bf16x3); V-frags via ldmatrix.trans of K tile ----
#pragma unroll
            for (int kb = 0; kb < 4; kb++) {
                uint32_t pah[4], pal[4];
                {
                    float p0 = sa[2 * kb][0],     p1 = sa[2 * kb][1];
                    float p2 = sa[2 * kb][2],     p3 = sa[2 * kb][3];
                    float p4 = sa[2 * kb + 1][0], p5 = sa[2 * kb + 1][1];
                    float p6 = sa[2 * kb + 1][2], p7 = sa[2 * kb + 1][3];
                    pah[0] = packbf(p0, p1); pah[1] = packbf(p2, p3);
                    pah[2] = packbf(p4, p5); pah[3] = packbf(p6, p7);
                    pal[0] = packbf(p0 - __uint_as_float(pah[0] << 16),
                                    p1 - __uint_as_float(pah[0] & 0xffff0000u));
                    pal[1] = packbf(p2 - __uint_as_float(pah[1] << 16),
                                    p3 - __uint_as_float(pah[1] & 0xffff0000u));
                    pal[2] = packbf(p4 - __uint_as_float(pah[2] << 16),
                                    p5 - __uint_as_float(pah[2] & 0xffff0000u));
                    pal[3] = packbf(p6 - __uint_as_float(pah[3] << 16),
                                    p7 - __uint_as_float(pah[3] & 0xffff0000u));
                }
#pragma unroll
                for (int nbp = 0; nbp < 4; nbp++) {
                    uint32_t off = kpv + (16 * kb * QS + 16 * nbp) * 2;
                    uint32_t vh[4], vl[4];
                    ldsm4t(vh, Kh_u + off);
                    ldsm4t(vl, Kl_u + off);
                    mma_bf16(Oa[2 * nbp],     pah, vh[0], vh[1]);
                    mma_bf16(Oa[2 * nbp],     pah, vl[0], vl[1]);
                    mma_bf16(Oa[2 * nbp],     pal, vh[0], vh[1]);
                    mma_bf16(Oa[2 * nbp + 1], pah, vh[2], vh[3]);
                    mma_bf16(Oa[2 * nbp + 1], pah, vl[2], vl[3]);
                    mma_bf16(Oa[2 * nbp + 1], pal, vh[2], vh[3]);
                }
            }
        }

        // ---- merge groups, write output ----
        __syncthreads();
        if (g == 1) {
#pragma unroll
            for (int nb = 0; nb < 8; nb++) {
                Om[rbase * 65 + 8 * nb + l2]           = Oa[nb][0];
                Om[rbase * 65 + 8 * nb + l2 + 1]       = Oa[nb][1];
                Om[(rbase + 8) * 65 + 8 * nb + l2]     = Oa[nb][2];
                Om[(rbase + 8) * 65 + 8 * nb + l2 + 1] = Oa[nb][3];
            }
            if ((lane & 3) == 0) {
                Mm[rbase] = mrow[0];     Lm[rbase] = lrow[0];
                Mm[rbase + 8] = mrow[1]; Lm[rbase + 8] = lrow[1];
            }
        }
        __syncthreads();
        if (g == 0) {
#pragma unroll
            for (int half = 0; half < 2; half++) {
                const int row = rbase + 8 * half;
                const float m1 = Mm[row], l1 = Lm[row];
                const float M  = fmaxf(mrow[half], m1);
                const float ea = __expf(mrow[half] - M);
                const float eb = __expf(m1 - M);
                const float inv = 1.f / (ea * lrow[half] + eb * l1);
                float* orow = &out[((size_t)b * NT + t0 + row) * NH];
#pragma unroll
                for (int nb = 0; nb < 8; nb++) {
                    int c = 8 * nb + l2;
                    float2 o2;
                    o2.x = (ea * Oa[nb][2 * half]     + eb * Om[row * 65 + c])     * inv;
                    o2.y = (ea * Oa[nb][2 * half + 1] + eb * Om[row * 65 + c + 1]) * inv;
                    *(float2*)&orow[c] = o2;
                }
            }
        }
    }
}

extern "C" void kernel_launch(void* const* d_in, const int* in_sizes, int n_in,
                              void* d_out, int out_size) {
    const float* x   = (const float*)d_in[0];
    const float* Wq  = (const float*)d_in[1];
    const float* rel = (const float*)d_in[2];
    float* out = (float*)d_out;

    static bool attr_set = false;
    if (!attr_set) {
        cudaFuncSetAttribute(flashT_kernel,
                             cudaFuncAttributeMaxDynamicSharedMemorySize, SMEM_BYTES);
        cudaFuncSetAttribute(projT_kernel,
                             cudaFuncAttributeMaxDynamicSharedMemorySize, PSMEM);
        attr_set = true;
    }

    prep_w_kernel<<<NC * NH / 256, 256>>>(Wq);
    projT_kernel<<<NB * NT / 128, 256, PSMEM>>>(x);

    dim3 grid(16, NB);
    flashT_kernel<<<grid, 256, SMEM_BYTES>>>(rel, out);
}

// round 6
// speedup vs baseline: 27.9763x; 1.0771x over previous
#include <cuda_runtime.h>
#include <cuda_bf16.h>
#include <cstdint>

#define NB 8
#define NT 2048
#define NC 768
#define NH 64
#define QS 72   // padded bf16 row stride for SMEM tiles

__device__ __align__(16) __nv_bfloat16 g_qh[NB * NT * NH];
__device__ __align__(16) __nv_bfloat16 g_ql[NB * NT * NH];

__device__ __forceinline__ uint32_t packbf(float e0, float e1) {
    uint32_t r;
    asm("cvt.rn.bf16x2.f32 %0, %1, %2;" : "=r"(r) : "f"(e1), "f"(e0));
    return r;   // lower 16 bits = e0, upper = e1
}

__device__ __forceinline__ void mma_bf16(float* d, const uint32_t* a,
                                         uint32_t b0, uint32_t b1) {
    asm volatile("mma.sync.aligned.m16n8k16.row.col.f32.bf16.bf16.f32 "
                 "{%0,%1,%2,%3}, {%4,%5,%6,%7}, {%8,%9}, {%0,%1,%2,%3};"
                 : "+f"(d[0]), "+f"(d[1]), "+f"(d[2]), "+f"(d[3])
                 : "r"(a[0]), "r"(a[1]), "r"(a[2]), "r"(a[3]),
                   "r"(b0), "r"(b1));
}

__device__ __forceinline__ void ldsm4(uint32_t* r, uint32_t addr) {
    asm volatile("ldmatrix.sync.aligned.m8n8.x4.shared.b16 {%0,%1,%2,%3}, [%4];"
                 : "=r"(r[0]), "=r"(r[1]), "=r"(r[2]), "=r"(r[3]) : "r"(addr));
}
__device__ __forceinline__ void ldsm4t(uint32_t* r, uint32_t addr) {
    asm volatile("ldmatrix.sync.aligned.m8n8.x4.trans.shared.b16 {%0,%1,%2,%3}, [%4];"
                 : "=r"(r[0]), "=r"(r[1]), "=r"(r[2]), "=r"(r[3]) : "r"(addr));
}

// ---------------------------------------------------------------------------
// Projection on tensor cores (bf16x3): q = x @ Wq, output split hi/lo.
// Wq fp32 split is fused into the staging loop (no prep kernel).
// ---------------------------------------------------------------------------
#define PSMEM ((128 + 128 + 64 + 64) * QS * 2)

__global__ __launch_bounds__(256) void projT_kernel(const float* __restrict__ x,
                                                    const float* __restrict__ Wq) {
    extern __shared__ char psm[];
    __nv_bfloat16* Xh = (__nv_bfloat16*)psm;
    __nv_bfloat16* Xl = Xh + 128 * QS;
    __nv_bfloat16* Wh = Xl + 128 * QS;
    __nv_bfloat16* Wl = Wh + 64 * QS;

    const int tid  = threadIdx.x;
    const int w    = tid >> 5;
    const int lane = tid & 31;
    const int quad = lane >> 3;
    const int l4   = lane >> 2;
    const int l2   = (lane & 3) << 1;
    const int r0   = blockIdx.x * 128;

    const uint32_t Xh_u = (uint32_t)__cvta_generic_to_shared(Xh);
    const uint32_t Xl_u = (uint32_t)__cvta_generic_to_shared(Xl);
    const uint32_t Wh_u = (uint32_t)__cvta_generic_to_shared(Wh);
    const uint32_t Wl_u = (uint32_t)__cvta_generic_to_shared(Wl);

    const uint32_t xa = ((16 * w + 8 * (quad & 1) + (lane & 7)) * QS + 8 * (quad >> 1)) * 2;
    const uint32_t wb = ((8 * (quad & 1) + (lane & 7)) * QS + 8 * (quad >> 1)) * 2;

    float Oacc[8][4];
#pragma unroll
    for (int nb = 0; nb < 8; nb++)
#pragma unroll
        for (int j = 0; j < 4; j++) Oacc[nb][j] = 0.f;

    for (int c0 = 0; c0 < NC; c0 += 64) {
        __syncthreads();
#pragma unroll
        for (int u = 0; u < 8; u++) {
            int e   = tid + u * 256;
            int row = e >> 4, g4 = e & 15;
            float4 v = *(const float4*)&x[(size_t)(r0 + row) * NC + c0 + g4 * 4];
            uint32_t h0 = packbf(v.x, v.y);
            uint32_t h1 = packbf(v.z, v.w);
            uint32_t l0 = packbf(v.x - __uint_as_float(h0 << 16),
                                 v.y - __uint_as_float(h0 & 0xffff0000u));
            uint32_t l1 = packbf(v.z - __uint_as_float(h1 << 16),
                                 v.w - __uint_as_float(h1 & 0xffff0000u));
            *(uint2*)&Xh[row * QS + g4 * 4] = make_uint2(h0, h1);
            *(uint2*)&Xl[row * QS + g4 * 4] = make_uint2(l0, l1);
        }
#pragma unroll
        for (int u = 0; u < 4; u++) {
            int e   = tid + u * 256;
            int row = e >> 4, g4 = e & 15;
            float4 v = *(const float4*)&Wq[(size_t)(c0 + row) * NH + g4 * 4];
            uint32_t h0 = packbf(v.x, v.y);
            uint32_t h1 = packbf(v.z, v.w);
            uint32_t l0 = packbf(v.x - __uint_as_float(h0 << 16),
                                 v.y - __uint_as_float(h0 & 0xffff0000u));
            uint32_t l1 = packbf(v.z - __uint_as_float(h1 << 16),
                                 v.w - __uint_as_float(h1 & 0xffff0000u));
            *(uint2*)&Wh[row * QS + g4 * 4] = make_uint2(h0, h1);
            *(uint2*)&Wl[row * QS + g4 * 4] = make_uint2(l0, l1);
        }
        __syncthreads();

        uint32_t ah[4][4], al[4][4];
#pragma unroll
        for (int ks = 0; ks < 4; ks++) {
            ldsm4(ah[ks], Xh_u + xa + 32 * ks);
            ldsm4(al[ks], Xl_u + xa + 32 * ks);
        }
#pragma unroll
        for (int ks = 0; ks < 4; ks++) {
#pragma unroll
            for (int nbp = 0; nbp < 4; nbp++) {
                uint32_t off = wb + (16 * ks * QS + 16 * nbp) * 2;
                uint32_t bh[4], bl[4];
                ldsm4t(bh, Wh_u + off);
                ldsm4t(bl, Wl_u + off);
                mma_bf16(Oacc[2 * nbp],     ah[ks], bh[0], bh[1]);
                mma_bf16(Oacc[2 * nbp],     ah[ks], bl[0], bl[1]);
                mma_bf16(Oacc[2 * nbp],     al[ks], bh[0], bh[1]);
                mma_bf16(Oacc[2 * nbp + 1], ah[ks], bh[2], bh[3]);
                mma_bf16(Oacc[2 * nbp + 1], ah[ks], bl[2], bl[3]);
                mma_bf16(Oacc[2 * nbp + 1], al[ks], bh[2], bh[3]);
            }
        }
    }

    const size_t row0 = (size_t)r0 + 16 * w + l4;
#pragma unroll
    for (int nb = 0; nb < 8; nb++) {
        int c = 8 * nb + l2;
        uint32_t hp0 = packbf(Oacc[nb][0], Oacc[nb][1]);
        uint32_t hp1 = packbf(Oacc[nb][2], Oacc[nb][3]);
        uint32_t lp0 = packbf(Oacc[nb][0] - __uint_as_float(hp0 << 16),
                              Oacc[nb][1] - __uint_as_float(hp0 & 0xffff0000u));
        uint32_t lp1 = packbf(Oacc[nb][2] - __uint_as_float(hp1 << 16),
                              Oacc[nb][3] - __uint_as_float(hp1 & 0xffff0000u));
        *(uint32_t*)&g_qh[row0 * NH + c]       = hp0;
        *(uint32_t*)&g_ql[row0 * NH + c]       = lp0;
        *(uint32_t*)&g_qh[(row0 + 8) * NH + c] = hp1;
        *(uint32_t*)&g_ql[(row0 + 8) * NH + c] = lp1;
    }
}

// ---------------------------------------------------------------------------
// Tensor-core flash attention, bf16x3, ldmatrix operands, V tile == K tile.
// No-max unnormalized softmax: scores bounded (|s|<~15), exp fits fp32,
// so O accumulates additively across tiles and groups; no rescaling.
// Block: 256 threads = 2 groups of 4 warps; pair-scheduled q-tiles.
// ---------------------------------------------------------------------------
#define SM_GRP0   18432
#define SM_GRPSZ  18944
#define SMEM_BYTES (SM_GRP0 + 2 * SM_GRPSZ)

__global__ __launch_bounds__(256) void flashT_kernel(const float* __restrict__ rel,
                                                     float* __restrict__ out) {
    extern __shared__ char smraw[];
    __nv_bfloat16* Qh = (__nv_bfloat16*)smraw;
    __nv_bfloat16* Ql = Qh + 64 * QS;

    const int tid  = threadIdx.x;
    const int w    = tid >> 5;
    const int lane = tid & 31;
    const int g    = w >> 2;
    const int wi   = w & 3;
    const int quad = lane >> 3;
    const int l4   = lane >> 2;
    const int l2   = (lane & 3) << 1;
    const int tid128 = tid & 127;

    char* gbase = smraw + SM_GRP0 + g * SM_GRPSZ;
    __nv_bfloat16* Kh = (__nv_bfloat16*)gbase;
    __nv_bfloat16* Kl = Kh + 64 * QS;
    float* bs = (float*)(gbase + 2 * 64 * QS * 2);

    float* Om = (float*)smraw;                 // [64][65] merge scratch
    float* Lm = (float*)(smraw + 16640);       // [64]

    const uint32_t Qh_u = (uint32_t)__cvta_generic_to_shared(Qh);
    const uint32_t Ql_u = (uint32_t)__cvta_generic_to_shared(Ql);
    const uint32_t Kh_u = (uint32_t)__cvta_generic_to_shared(Kh);
    const uint32_t Kl_u = (uint32_t)__cvta_generic_to_shared(Kl);

    const uint32_t qa  = ((16 * wi + 8 * (quad & 1) + (lane & 7)) * QS + 8 * (quad >> 1)) * 2;
    const uint32_t kqk = ((8 * (quad >> 1) + (lane & 7)) * QS + 8 * (quad & 1)) * 2;
    const uint32_t kpv = ((8 * (quad & 1) + (lane & 7)) * QS + 8 * (quad >> 1)) * 2;

    const int b    = blockIdx.y;
    const int pair = blockIdx.x;
    const int rbase = 16 * wi + l4;

    for (int pi = 0; pi < 2; pi++) {
        const int tile = (pi == 0) ? (31 - pair) : pair;
        const int t0   = tile * 64;
        __syncthreads();
        // stage Q hi/lo
        {
            const __nv_bfloat16* sh = &g_qh[((size_t)b * NT + t0) * NH];
            const __nv_bfloat16* sl = &g_ql[((size_t)b * NT + t0) * NH];
#pragma unroll
            for (int u = 0; u < 2; u++) {
                int e   = tid + u * 256;
                int row = e >> 3, q4 = e & 7;
                *(uint4*)&Qh[row * QS + q4 * 8] = *(const uint4*)&sh[row * 64 + q4 * 8];
                *(uint4*)&Ql[row * QS + q4 * 8] = *(const uint4*)&sl[row * 64 + q4 * 8];
            }
        }
        __syncthreads();

        uint32_t qfh[4][4], qfl[4][4];
#pragma unroll
        for (int ks = 0; ks < 4; ks++) {
            ldsm4(qfh[ks], Qh_u + qa + 32 * ks);
            ldsm4(qfl[ks], Ql_u + qa + 32 * ks);
        }

        float Oa[8][4];
#pragma unroll
        for (int nb = 0; nb < 8; nb++)
#pragma unroll
            for (int j = 0; j < 4; j++) Oa[nb][j] = 0.f;
        float lrow[2] = {0.f, 0.f};

        for (int kt = g; kt <= tile; kt += 2) {
            const int s0 = kt * 64;
            asm volatile("bar.sync %0, %1;" :: "r"(1 + g), "r"(128) : "memory");
            // stage K (== V) natural layout, hi/lo
            {
                const __nv_bfloat16* kh = &g_qh[((size_t)b * NT + s0) * NH];
                const __nv_bfloat16* kl = &g_ql[((size_t)b * NT + s0) * NH];
#pragma unroll
                for (int u = 0; u < 4; u++) {
                    int e   = tid128 + u * 128;
                    int row = e >> 3, q4 = e & 7;
                    *(uint4*)&Kh[row * QS + q4 * 8] = *(const uint4*)&kh[row * 64 + q4 * 8];
                    *(uint4*)&Kl[row * QS + q4 * 8] = *(const uint4*)&kl[row * 64 + q4 * 8];
                }
                if (tid128 < 127) bs[tid128] = rel[s0 - t0 + 1984 + tid128];
            }
            asm volatile("bar.sync %0, %1;" :: "r"(1 + g), "r"(128) : "memory");

            // ---- S = Q K^T (bf16x3) ----
            float sa[8][4];
#pragma unroll
            for (int nb = 0; nb < 8; nb++)
#pragma unroll
                for (int j = 0; j < 4; j++) sa[nb][j] = 0.f;
#pragma unroll
            for (int ks = 0; ks < 4; ks++) {
#pragma unroll
                for (int nbp = 0; nbp < 4; nbp++) {
                    uint32_t off = kqk + (16 * nbp * QS + 16 * ks) * 2;
                    uint32_t bh[4], bl[4];
                    ldsm4(bh, Kh_u + off);
                    ldsm4(bl, Kl_u + off);
                    mma_bf16(sa[2 * nbp],     qfh[ks], bh[0], bh[1]);
                    mma_bf16(sa[2 * nbp],     qfh[ks], bl[0], bl[1]);
                    mma_bf16(sa[2 * nbp],     qfl[ks], bh[0], bh[1]);
                    mma_bf16(sa[2 * nbp + 1], qfh[ks], bh[2], bh[3]);
                    mma_bf16(sa[2 * nbp + 1], qfh[ks], bl[2], bl[3]);
                    mma_bf16(sa[2 * nbp + 1], qfl[ks], bh[2], bh[3]);
                }
            }

            // ---- bias + causal mask + exp (no max subtraction) ----
            const bool diag = (kt == tile);
#pragma unroll
            for (int nb = 0; nb < 8; nb++) {
                int c0 = 8 * nb + l2;
                float p0 = __expf(fmaf(sa[nb][0], 0.125f, bs[c0 - rbase + 63]));
                float p1 = __expf(fmaf(sa[nb][1], 0.125f, bs[c0 - rbase + 64]));
                float p2 = __expf(fmaf(sa[nb][2], 0.125f, bs[c0 - rbase + 55]));
                float p3 = __expf(fmaf(sa[nb][3], 0.125f, bs[c0 - rbase + 56]));
                if (diag) {
                    if (c0 > rbase)         p0 = 0.f;
                    if (c0 + 1 > rbase)     p1 = 0.f;
                    if (c0 > rbase + 8)     p2 = 0.f;
                    if (c0 + 1 > rbase + 8) p3 = 0.f;
                }
                sa[nb][0] = p0; sa[nb][1] = p1; sa[nb][2] = p2; sa[nb][3] = p3;
                lrow[0] += p0 + p1;
                lrow[1] += p2 + p3;
            }

            // ---- O += P V (bf16x3); V-frags via ldmatrix.trans of K tile ----
#pragma unroll
            for (int kb = 0; kb < 4; kb++) {
                uint32_t pah[4], pal[4];
                {
                    float p0 = sa[2 * kb][0],     p1 = sa[2 * kb][1];
                    float p2 = sa[2 * kb][2],     p3 = sa[2 * kb][3];
                    float p4 = sa[2 * kb + 1][0], p5 = sa[2 * kb + 1][1];
                    float p6 = sa[2 * kb + 1][2], p7 = sa[2 * kb + 1][3];
                    pah[0] = packbf(p0, p1); pah[1] = packbf(p2, p3);
                    pah[2] = packbf(p4, p5); pah[3] = packbf(p6, p7);
                    pal[0] = packbf(p0 - __uint_as_float(pah[0] << 16),
                                    p1 - __uint_as_float(pah[0] & 0xffff0000u));
                    pal[1] = packbf(p2 - __uint_as_float(pah[1] << 16),
                                    p3 - __uint_as_float(pah[1] & 0xffff0000u));
                    pal[2] = packbf(p4 - __uint_as_float(pah[2] << 16),
                                    p5 - __uint_as_float(pah[2] & 0xffff0000u));
                    pal[3] = packbf(p6 - __uint_as_float(pah[3] << 16),
                                    p7 - __uint_as_float(pah[3] & 0xffff0000u));
                }
#pragma unroll
                for (int nbp = 0; nbp < 4; nbp++) {
                    uint32_t off = kpv + (16 * kb * QS + 16 * nbp) * 2;
                    uint32_t vh[4], vl[4];
                    ldsm4t(vh, Kh_u + off);
                    ldsm4t(vl, Kl_u + off);
                    mma_bf16(Oa[2 * nbp],     pah, vh[0], vh[1]);
                    mma_bf16(Oa[2 * nbp],     pah, vl[0], vl[1]);
                    mma_bf16(Oa[2 * nbp],     pal, vh[0], vh[1]);
                    mma_bf16(Oa[2 * nbp + 1], pah, vh[2], vh[3]);
                    mma_bf16(Oa[2 * nbp + 1], pah, vl[2], vl[3]);
                    mma_bf16(Oa[2 * nbp + 1], pal, vh[2], vh[3]);
                }
            }
        }

        // reduce row sums over the 4 lanes sharing a row
        lrow[0] += __shfl_xor_sync(0xffffffffu, lrow[0], 1);
        lrow[0] += __shfl_xor_sync(0xffffffffu, lrow[0], 2);
        lrow[1] += __shfl_xor_sync(0xffffffffu, lrow[1], 1);
        lrow[1] += __shfl_xor_sync(0xffffffffu, lrow[1], 2);

        // ---- merge the two groups' partials (pure addition), write out ----
        __syncthreads();
        if (g == 1) {
#pragma unroll
            for (int nb = 0; nb < 8; nb++) {
                Om[rbase * 65 + 8 * nb + l2]           = Oa[nb][0];
                Om[rbase * 65 + 8 * nb + l2 + 1]       = Oa[nb][1];
                Om[(rbase + 8) * 65 + 8 * nb + l2]     = Oa[nb][2];
                Om[(rbase + 8) * 65 + 8 * nb + l2 + 1] = Oa[nb][3];
            }
            if ((lane & 3) == 0) {
                Lm[rbase]     = lrow[0];
                Lm[rbase + 8] = lrow[1];
            }
        }
        __syncthreads();
        if (g == 0) {
#pragma unroll
            for (int half = 0; half < 2; half++) {
                const int row = rbase + 8 * half;
                const float inv = 1.f / (lrow[half] + Lm[row]);
                float* orow = &out[((size_t)b * NT + t0 + row) * NH];
#pragma unroll
                for (int nb = 0; nb < 8; nb++) {
                    int c = 8 * nb + l2;
                    float2 o2;
                    o2.x = (Oa[nb][2 * half]     + Om[row * 65 + c])     * inv;
                    o2.y = (Oa[nb][2 * half + 1] + Om[row * 65 + c + 1]) * inv;
                    *(float2*)&orow[c] = o2;
                }
            }
        }
    }
}

extern "C" void kernel_launch(void* const* d_in, const int* in_sizes, int n_in,
                              void* d_out, int out_size) {
    const float* x   = (const float*)d_in[0];
    const float* Wq  = (const float*)d_in[1];
    const float* rel = (const float*)d_in[2];
    float* out = (float*)d_out;

    static bool attr_set = false;
    if (!attr_set) {
        cudaFuncSetAttribute(flashT_kernel,
                             cudaFuncAttributeMaxDynamicSharedMemorySize, SMEM_BYTES);
        cudaFuncSetAttribute(projT_kernel,
                             cudaFuncAttributeMaxDynamicSharedMemorySize, PSMEM);
        attr_set = true;
    }

    projT_kernel<<<NB * NT / 128, 256, PSMEM>>>(x, Wq);

    dim3 grid(16, NB);
    flashT_kernel<<<grid, 256, SMEM_BYTES>>>(rel, out);
}